// round 14
// baseline (speedup 1.0000x reference)
#include <cuda_runtime.h>

#define E_NUM 8192
#define D 64
#define NBLK 128                    // <= 148 SMs, all co-resident (1 block/SM)
#define THR 256
#define WPB 8                       // warps per block
#define EVW 8                       // events per warp: 128*8*8 = 8192
#define WST 66                      // weight row stride in ull (33 float4, odd -> conflict-free)
#define LW_ULL (32 * WST)           // 2112 ull per layer

typedef unsigned long long ull;

// ---- dynamic smem layout (bytes) ----
#define SM_W     0                                  // 5 * 2112 ull = 84480
#define SM_TILE  (5 * LW_ULL * 8)                   // 8 warps * 256 ull = 16384
#define SM_WSUM  (SM_TILE + WPB * 256 * 8)          // 8*64 floats = 2048
#define SM_B     (SM_WSUM + WPB * D * 4)            // 5*64 floats = 1280
#define SM_B0F   (SM_B + 5 * D * 4)                 // 64 floats (r1b0)
#define SM_UV    (SM_B0F + D * 4)                   // u[64], v[64]
#define SM_FIN   (SM_UV + 2 * D * 4)                // 3*64 floats (also scp/scm temp)
#define SM_MISC  (SM_FIN + 3 * D * 4)               // s_last int
#define SMEM_ALL (SM_MISC + 16)                     // ~105.7 KB

// ---------------- scratch (no allocs allowed) ----------------
__device__ float g_zero[2 * E_NUM + D];     // P, M, gsum — zeroed by memset node
#define g_P      (g_zero)
#define g_M      (g_zero + E_NUM)
#define g_gsum   (g_zero + 2 * E_NUM)
__device__ float g_pooled[E_NUM * D];       // generic path only (zeroed in-kernel)
__device__ int   g_cnt0, g_cnt1, g_cnt2;    // barriers/tickets (self-resetting)

// ---- packed f32x2 helpers ----
__device__ __forceinline__ void ffma2(ull& d, ull a, ull b)
{
    asm("fma.rn.f32x2 %0, %1, %2, %0;" : "+l"(d) : "l"(a), "l"(b));
}
__device__ __forceinline__ ull dup2(float w)
{
    ull d; asm("mov.b64 %0, {%1, %1};" : "=l"(d) : "f"(w)); return d;
}
__device__ __forceinline__ ull pack2(float lo, float hi)
{
    ull d; asm("mov.b64 %0, {%1, %2};" : "=l"(d) : "f"(lo), "f"(hi)); return d;
}
__device__ __forceinline__ void unpk2(ull d, float& lo, float& hi)
{
    asm("mov.b64 {%0, %1}, %2;" : "=f"(lo), "=f"(hi) : "l"(d));
}

// grid-wide spin barrier (all NBLK blocks are co-resident by construction)
__device__ __forceinline__ void grid_barrier(int* cnt, int tid)
{
    __threadfence();
    __syncthreads();
    if (tid == 0) {
        atomicAdd(cnt, 1);
        while (*(volatile int*)cnt < NBLK) __nanosleep(64);
    }
    __syncthreads();
}

// transposed weight load: dst[k2*WST + j] = (W[j][2k2], W[j][2k2+1])
__device__ __forceinline__ void loadW(ull* __restrict__ dst,
                                      const float* __restrict__ src, int tid)
{
    #pragma unroll
    for (int s = 0; s < 8; s++) {
        int i  = tid + s * THR;       // 0..2047
        int k2 = i & 31;
        int j  = i >> 5;
        float2 w = *(const float2*)&src[j * D + 2 * k2];
        *(float2*)&dst[k2 * WST + j] = w;
    }
}

// ---------------- THE kernel: stage1 + events + final, persistent ----------------
__global__ void __launch_bounds__(THR) k_all(
    const float* __restrict__ x, const int* __restrict__ seg, int n,
    const float* __restrict__ p1w0, const float* __restrict__ p1b0,
    const float* __restrict__ p1w1, const float* __restrict__ p1b1,
    const float* __restrict__ r1w0, const float* __restrict__ r1b0,
    const float* __restrict__ r1w1, const float* __restrict__ r1b1,
    const float* __restrict__ o1w,  const float* __restrict__ o1b,
    const float* __restrict__ p2w0, const float* __restrict__ p2b0,
    const float* __restrict__ p2w1, const float* __restrict__ p2b1,
    const float* __restrict__ r2w0, const float* __restrict__ r2b0,
    const float* __restrict__ r2w1, const float* __restrict__ r2b1,
    const float* __restrict__ o2w,  const float* __restrict__ o2b,
    float* __restrict__ out)
{
    extern __shared__ __align__(16) char dsm[];
    ull*   sWall = (ull*)(dsm + SM_W);
    ull*   tiles = (ull*)(dsm + SM_TILE);
    float* wsum  = (float*)(dsm + SM_WSUM);
    float* sB    = (float*)(dsm + SM_B);
    float* sb0f  = (float*)(dsm + SM_B0F);
    float* su    = (float*)(dsm + SM_UV);
    float* sv    = (float*)(dsm + SM_UV + D * 4);
    float* sfin  = (float*)(dsm + SM_FIN);
    int*   s_lastp = (int*)(dsm + SM_MISC);

    const int tid  = threadIdx.x;
    const int wid  = tid >> 5;
    const int lane = tid & 31;
    const int f0   = 2 * lane;

    // ---- flag: are phi1 biases nonzero? (uniform across blocks) ----
    int nz = 0;
    if (tid < D) nz = (p1b0[tid] != 0.f) || (p1b1[tid] != 0.f);
    const int flag = __syncthreads_or(nz);

    const float* Ws[5];
    const float* Bs[5];
    int NL;
    if (!flag) {
        Ws[0] = r1w1; Bs[0] = r1b1;
        Ws[1] = o1w;  Bs[1] = o1b;
        Ws[2] = p2w0; Bs[2] = p2b0;
        Ws[3] = p2w1; Bs[3] = p2b1;
        NL = 4;
    } else {
        Ws[0] = r1w0; Bs[0] = r1b0;
        Ws[1] = r1w1; Bs[1] = r1b1;
        Ws[2] = o1w;  Bs[2] = o1b;
        Ws[3] = p2w0; Bs[3] = p2b0;
        Ws[4] = p2w1; Bs[4] = p2b1;
        NL = 5;
    }

    // ---- phase A0: issue weight loads early (complete under stage1) ----
    for (int L = 0; L < NL; L++) loadW(sWall + L * LW_ULL, Ws[L], tid);
    for (int i = tid; i < NL * D; i += THR) sB[i] = Bs[i >> 6][i & 63];
    if (tid < D) sb0f[tid] = r1b0[tid];

    // ---- per-block u,v (folded phi1+pool+rho1-layer1), uses sfin as temp ----
    {
        float* scp = sfin;
        float* scm = sfin + D;
        if (tid < D) {
            float vp = 0.f, vn = 0.f;
            #pragma unroll
            for (int j = 0; j < D; j++) {
                float w   = p1w0[j];
                float col = p1w1[j * D + tid];
                vp += fmaxf(w, 0.f)  * col;
                vn += fmaxf(-w, 0.f) * col;
            }
            scp[tid] = fmaxf(vp, 0.f);
            scm[tid] = fmaxf(vn, 0.f);
        }
        __syncthreads();
        if (tid < D) {
            float u = 0.f, v = 0.f;
            #pragma unroll
            for (int j = 0; j < D; j++) {
                float w = r1w0[j * D + tid];
                u += scp[j] * w;
                v += scm[j] * w;
            }
            su[tid] = u;
            sv[tid] = v;
        }
    }

    // ---- phase A1: stage-1 segment sums ----
    if (!flag) {
        // S = sum(x), A = sum(|x|); P=(A+S)/2, M=(A-S)/2
        const int warp   = (blockIdx.x * THR + tid) >> 5;
        const int nwarps = (NBLK * THR) >> 5;       // 1024
        const int G      = n >> 2;
        const int gpw    = (G + nwarps - 1) / nwarps;

        const long long gbase = (long long)warp * gpw;
        const long long gend0 = gbase + gpw;
        const long long gend  = gend0 < (long long)G ? gend0 : (long long)G;

        const float4* x4 = (const float4*)x;
        const int4*   s4 = (const int4*)seg;

        int   cur = -1;
        float S = 0.f, A = 0.f;

        for (long long g = gbase + lane; g < gend; g += 32) {
            float4 xv = x4[g];
            int4   sv4 = s4[g];
            if ((sv4.x == sv4.w) && (sv4.x == cur)) {
                S += (xv.x + xv.y) + (xv.z + xv.w);
                A += (fabsf(xv.x) + fabsf(xv.y)) + (fabsf(xv.z) + fabsf(xv.w));
            } else {
                int   ss[4] = {sv4.x, sv4.y, sv4.z, sv4.w};
                float xs[4] = {xv.x, xv.y, xv.z, xv.w};
                #pragma unroll
                for (int u2 = 0; u2 < 4; u2++) {
                    if (ss[u2] != cur) {
                        if (cur >= 0) {
                            atomicAdd(&g_P[cur], 0.5f * (A + S));
                            atomicAdd(&g_M[cur], 0.5f * (A - S));
                        }
                        cur = ss[u2]; S = 0.f; A = 0.f;
                    }
                    S += xs[u2]; A += fabsf(xs[u2]);
                }
            }
        }
        if (cur >= 0) {
            atomicAdd(&g_P[cur], 0.5f * (A + S));
            atomicAdd(&g_M[cur], 0.5f * (A - S));
        }

        if (warp == 0 && lane == 0) {
            for (int i = G * 4; i < n; i++) {
                float xv = x[i]; int s = seg[i];
                atomicAdd(&g_P[s], fmaxf(xv,  0.f));
                atomicAdd(&g_M[s], fmaxf(-xv, 0.f));
            }
        }
    } else {
        // generic fallback: zero my pooled slice, barrier, then phi+pool with atomics
        const int slice = E_NUM * D / NBLK;
        float* myz = g_pooled + blockIdx.x * slice;
        for (int i = tid; i < slice; i += THR) myz[i] = 0.f;
        grid_barrier(&g_cnt0, tid);

        float h1[D];
        const int stride = NBLK * THR;
        for (int i = blockIdx.x * THR + tid; i < n; i += stride) {
            float xv = x[i];
            int   e  = seg[i];
            #pragma unroll
            for (int j = 0; j < D; j++) h1[j] = fmaxf(xv * p1w0[j] + p1b0[j], 0.f);
            #pragma unroll 2
            for (int k = 0; k < D; k++) {
                float acc = p1b1[k];
                #pragma unroll
                for (int j = 0; j < D; j++) acc += h1[j] * p1w1[j * D + k];
                atomicAdd(&g_pooled[e * D + k], fmaxf(acc, 0.f));
            }
        }
    }

    // ---- grid barrier: all segment sums complete ----
    grid_barrier(&g_cnt1, tid);

    // ---- phase B: warp-autonomous event MLP (weights already in smem) ----
    ull* tile = tiles + wid * 256;            // [pair 0..3][feat 0..63]
    const int e0 = (blockIdx.x * WPB + wid) * EVW;

    if (!flag) {
        float4 Pa = make_float4(__ldcg(&g_P[e0+0]), __ldcg(&g_P[e0+1]),
                                __ldcg(&g_P[e0+2]), __ldcg(&g_P[e0+3]));
        float4 Pb = make_float4(__ldcg(&g_P[e0+4]), __ldcg(&g_P[e0+5]),
                                __ldcg(&g_P[e0+6]), __ldcg(&g_P[e0+7]));
        float4 Ma = make_float4(__ldcg(&g_M[e0+0]), __ldcg(&g_M[e0+1]),
                                __ldcg(&g_M[e0+2]), __ldcg(&g_M[e0+3]));
        float4 Mb = make_float4(__ldcg(&g_M[e0+4]), __ldcg(&g_M[e0+5]),
                                __ldcg(&g_M[e0+6]), __ldcg(&g_M[e0+7]));
        float u0 = su[f0], u1 = su[f0 + 1];
        float v0 = sv[f0], v1 = sv[f0 + 1];
        float b0f = sb0f[f0], b1f = sb0f[f0 + 1];
        float Pv[8] = {Pa.x, Pa.y, Pa.z, Pa.w, Pb.x, Pb.y, Pb.z, Pb.w};
        float Mv[8] = {Ma.x, Ma.y, Ma.z, Ma.w, Mb.x, Mb.y, Mb.z, Mb.w};
        #pragma unroll
        for (int p = 0; p < 4; p++) {
            float lo0 = fmaxf(Pv[2*p]   * u0 + Mv[2*p]   * v0 + b0f, 0.f);
            float hi0 = fmaxf(Pv[2*p+1] * u0 + Mv[2*p+1] * v0 + b0f, 0.f);
            float lo1 = fmaxf(Pv[2*p]   * u1 + Mv[2*p]   * v1 + b1f, 0.f);
            float hi1 = fmaxf(Pv[2*p+1] * u1 + Mv[2*p+1] * v1 + b1f, 0.f);
            ulonglong2 st; st.x = pack2(lo0, hi0); st.y = pack2(lo1, hi1);
            *(ulonglong2*)&tile[p * D + f0] = st;
        }
    } else {
        #pragma unroll
        for (int p = 0; p < 4; p++) {
            ulonglong2 st;
            st.x = pack2(__ldcg(&g_pooled[(e0 + 2*p)     * D + f0]),
                         __ldcg(&g_pooled[(e0 + 2*p + 1) * D + f0]));
            st.y = pack2(__ldcg(&g_pooled[(e0 + 2*p)     * D + f0 + 1]),
                         __ldcg(&g_pooled[(e0 + 2*p + 1) * D + f0 + 1]));
            *(ulonglong2*)&tile[p * D + f0] = st;
        }
    }
    __syncwarp();

    for (int L = 0; L < NL; L++) {
        const ull* cw = sWall + L * LW_ULL + lane * WST;
        float bf0 = sB[L * D + f0], bf1 = sB[L * D + f0 + 1];
        ull a0[4], a1[4];
        #pragma unroll
        for (int p = 0; p < 4; p++) { a0[p] = dup2(bf0); a1[p] = dup2(bf1); }

        #pragma unroll 8
        for (int j = 0; j < D; j += 2) {
            ulonglong2 lw = *(const ulonglong2*)&cw[j];
            float wja, wjb, wka, wkb;
            unpk2(lw.x, wja, wjb);
            unpk2(lw.y, wka, wkb);
            ull wj0 = dup2(wja), wj1 = dup2(wjb);
            ull wk0 = dup2(wka), wk1 = dup2(wkb);
            #pragma unroll
            for (int p = 0; p < 4; p++) {
                ulonglong2 t = *(const ulonglong2*)&tile[p * D + j];  // broadcast
                ffma2(a0[p], t.x, wj0); ffma2(a1[p], t.x, wj1);
                ffma2(a0[p], t.y, wk0); ffma2(a1[p], t.y, wk1);
            }
        }

        if (L < NL - 1) {
            __syncwarp();
            #pragma unroll
            for (int p = 0; p < 4; p++) {
                float lo, hi;
                ulonglong2 st;
                unpk2(a0[p], lo, hi); st.x = pack2(fmaxf(lo,0.f), fmaxf(hi,0.f));
                unpk2(a1[p], lo, hi); st.y = pack2(fmaxf(lo,0.f), fmaxf(hi,0.f));
                *(ulonglong2*)&tile[p * D + f0] = st;
            }
            __syncwarp();
        } else {
            float sA = 0.f, sBv = 0.f, lo, hi;
            #pragma unroll
            for (int p = 0; p < 4; p++) {
                unpk2(a0[p], lo, hi); sA  += fmaxf(lo,0.f) + fmaxf(hi,0.f);
                unpk2(a1[p], lo, hi); sBv += fmaxf(lo,0.f) + fmaxf(hi,0.f);
            }
            wsum[wid * D + f0]     = sA;
            wsum[wid * D + f0 + 1] = sBv;
        }
    }

    __syncthreads();
    if (tid < D) {
        float tot = 0.f;
        #pragma unroll
        for (int w = 0; w < WPB; w++) tot += wsum[w * D + tid];
        atomicAdd(&g_gsum[tid], tot);
    }

    // ---- last-block ticket: rho2 + output ----
    __threadfence();
    __syncthreads();
    if (tid == 0) {
        int old = atomicAdd(&g_cnt2, 1);
        *s_lastp = (old == NBLK - 1);
    }
    __syncthreads();

    if (*s_lastp) {
        float* sf0 = sfin, *sf1 = sfin + D, *sf2 = sfin + 2 * D;
        if (tid < D) sf0[tid] = __ldcg(&g_gsum[tid]);
        __syncthreads();
        if (tid < D) {
            float a = r2b0[tid];
            #pragma unroll
            for (int j = 0; j < D; j++) a += sf0[j] * r2w0[j * D + tid];
            sf1[tid] = fmaxf(a, 0.f);
        }
        __syncthreads();
        if (tid < D) {
            float a = r2b1[tid];
            #pragma unroll
            for (int j = 0; j < D; j++) a += sf1[j] * r2w1[j * D + tid];
            sf2[tid] = fmaxf(a, 0.f);
        }
        __syncthreads();
        if (tid < 10) {
            float a = o2b[tid];
            #pragma unroll
            for (int j = 0; j < D; j++) a += sf2[j] * o2w[j * 10 + tid];
            out[tid] = a;
        }
        if (tid == 0) { g_cnt0 = 0; g_cnt1 = 0; g_cnt2 = 0; }  // reset for next replay
    }
}

// ---------------- launch ----------------
extern "C" void kernel_launch(void* const* d_in, const int* in_sizes, int n_in,
                              void* d_out, int out_size)
{
    const float* x    = (const float*)d_in[0];
    const int*   seg  = (const int*)  d_in[1];
    const float* p1w0 = (const float*)d_in[2];
    const float* p1b0 = (const float*)d_in[3];
    const float* p1w1 = (const float*)d_in[4];
    const float* p1b1 = (const float*)d_in[5];
    const float* r1w0 = (const float*)d_in[6];
    const float* r1b0 = (const float*)d_in[7];
    const float* r1w1 = (const float*)d_in[8];
    const float* r1b1 = (const float*)d_in[9];
    const float* o1w  = (const float*)d_in[10];
    const float* o1b  = (const float*)d_in[11];
    const float* p2w0 = (const float*)d_in[12];
    const float* p2b0 = (const float*)d_in[13];
    const float* p2w1 = (const float*)d_in[14];
    const float* p2b1 = (const float*)d_in[15];
    const float* r2w0 = (const float*)d_in[16];
    const float* r2b0 = (const float*)d_in[17];
    const float* r2w1 = (const float*)d_in[18];
    const float* r2b1 = (const float*)d_in[19];
    const float* o2w  = (const float*)d_in[20];
    const float* o2b  = (const float*)d_in[21];
    const int n = in_sizes[0];

    cudaFuncSetAttribute(k_all,
                         cudaFuncAttributeMaxDynamicSharedMemorySize, SMEM_ALL);

    void* zp = nullptr;
    cudaGetSymbolAddress(&zp, g_zero);
    cudaMemsetAsync(zp, 0, sizeof(float) * (2 * E_NUM + D));

    k_all<<<NBLK, THR, SMEM_ALL>>>(x, seg, n,
                                   p1w0, p1b0, p1w1, p1b1,
                                   r1w0, r1b0, r1w1, r1b1,
                                   o1w, o1b, p2w0, p2b0, p2w1, p2b1,
                                   r2w0, r2b0, r2w1, r2b1,
                                   o2w, o2b, (float*)d_out);
}

// round 16
// speedup vs baseline: 1.0907x; 1.0907x over previous
#include <cuda_runtime.h>
#include <cstdint>

#define E_NUM 8192
#define D 64
#define S1_BLOCKS 592
#define EB 64                       // events per block
#define NBLK_EV (E_NUM / EB)        // 128
#define EV_THR 256
#define AST 68                      // A tile row stride (floats): 4*gr+km conflict-free
#define LW_F2 2112                  // f2 per layer: 8 kstep * (4 km * 66)
#define KMST 66                     // km stride in f2

// ---- events-kernel dynamic smem layout (bytes) ----
#define SM_A    0                       // 64 * 68 * 4 = 17408
#define SM_W    17408                   // 5 * 2112 * 8 = 84480
#define SM_B    (SM_W + 5 * LW_F2 * 8)  // 5*64*4 = 1280
#define SM_UV   (SM_B + 5 * D * 4)      // su, sv, sb0f = 768
#define SM_LAST (SM_UV + 3 * D * 4)
#define SMEM_EV (SM_LAST + 16)

// ---------------- scratch (no allocs allowed) ----------------
__device__ float g_zero[2 * E_NUM + D + E_NUM * D];
#define g_P      (g_zero)
#define g_M      (g_zero + E_NUM)
#define g_gsum   (g_zero + 2 * E_NUM)
#define g_pooled (g_zero + 2 * E_NUM + D)

__device__ float g_u[D], g_v[D];
__device__ int   g_flag;
__device__ int   g_cnt;

// ---- helpers ----
__device__ __forceinline__ uint32_t tf32r(float f)
{
    uint32_t r; asm("cvt.rna.tf32.f32 %0, %1;" : "=r"(r) : "f"(f)); return r;
}
__device__ __forceinline__ void mma_tf32(float& c0, float& c1, float& c2, float& c3,
                                         uint32_t a0, uint32_t a1, uint32_t a2, uint32_t a3,
                                         uint32_t b0, uint32_t b1)
{
    asm volatile(
        "mma.sync.aligned.m16n8k8.row.col.f32.tf32.tf32.f32 "
        "{%0,%1,%2,%3}, {%4,%5,%6,%7}, {%8,%9}, {%0,%1,%2,%3};"
        : "+f"(c0), "+f"(c1), "+f"(c2), "+f"(c3)
        : "r"(a0), "r"(a1), "r"(a2), "r"(a3), "r"(b0), "r"(b1));
}

// ---------------- K1: stage-1 segment sums (prefetch-pipelined) + prep ----------------
__global__ void __launch_bounds__(256) k_stage1(
    const float* __restrict__ x, const int* __restrict__ seg, int n,
    const float* __restrict__ w0, const float* __restrict__ b0,
    const float* __restrict__ W1, const float* __restrict__ b1,
    const float* __restrict__ r1w0)
{
    const int tid = threadIdx.x;
    __shared__ float scp[D], scm[D];

    int nz = 0;
    if (tid < D) nz = (b0[tid] != 0.f) || (b1[tid] != 0.f);
    const int anyb = __syncthreads_or(nz);

    if (blockIdx.x == 0) {
        if (tid == 0) g_flag = anyb;
        if (tid < D) {
            float vp = 0.f, vn = 0.f;
            #pragma unroll
            for (int j = 0; j < D; j++) {
                float w   = w0[j];
                float col = W1[j * D + tid];
                vp += fmaxf(w, 0.f)  * col;
                vn += fmaxf(-w, 0.f) * col;
            }
            scp[tid] = fmaxf(vp, 0.f);
            scm[tid] = fmaxf(vn, 0.f);
        }
        __syncthreads();
        if (tid < D) {
            float u = 0.f, v = 0.f;
            #pragma unroll
            for (int j = 0; j < D; j++) {
                float w = r1w0[j * D + tid];
                u += scp[j] * w;
                v += scm[j] * w;
            }
            g_u[tid] = u;
            g_v[tid] = v;
        }
    }

    if (!anyb) {
        const int lane   = tid & 31;
        const int warp   = (blockIdx.x * blockDim.x + tid) >> 5;
        const int nwarps = (gridDim.x * blockDim.x) >> 5;
        const int G      = n >> 2;
        const int gpw    = (G + nwarps - 1) / nwarps;

        const long long gbase = (long long)warp * gpw;
        const long long gend0 = gbase + gpw;
        const long long gend  = gend0 < (long long)G ? gend0 : (long long)G;

        const float4* x4 = (const float4*)x;
        const int4*   s4 = (const int4*)seg;

        int   cur = -1;
        float S = 0.f, A = 0.f;

        auto process = [&](const float4& xv, const int4& sv4) {
            if ((sv4.x == sv4.w) && (sv4.x == cur)) {
                S += (xv.x + xv.y) + (xv.z + xv.w);
                A += (fabsf(xv.x) + fabsf(xv.y)) + (fabsf(xv.z) + fabsf(xv.w));
            } else {
                int   ss[4] = {sv4.x, sv4.y, sv4.z, sv4.w};
                float xs[4] = {xv.x, xv.y, xv.z, xv.w};
                #pragma unroll
                for (int u2 = 0; u2 < 4; u2++) {
                    if (ss[u2] != cur) {
                        if (cur >= 0) {
                            atomicAdd(&g_P[cur], 0.5f * (A + S));
                            atomicAdd(&g_M[cur], 0.5f * (A - S));
                        }
                        cur = ss[u2]; S = 0.f; A = 0.f;
                    }
                    S += xs[u2]; A += fabsf(xs[u2]);
                }
            }
        };

        long long g = gbase + lane;
        if (g < gend) {
            float4 xv = x4[g];
            int4   sv4 = s4[g];
            for (g += 32; g < gend; g += 32) {
                float4 xn = x4[g];      // prefetch next (overlaps process)
                int4   sn = s4[g];
                process(xv, sv4);
                xv = xn; sv4 = sn;
            }
            process(xv, sv4);
            if (cur >= 0) {
                atomicAdd(&g_P[cur], 0.5f * (A + S));
                atomicAdd(&g_M[cur], 0.5f * (A - S));
            }
        }

        if (warp == 0 && lane == 0) {
            for (int i = G * 4; i < n; i++) {
                float xv = x[i]; int s = seg[i];
                atomicAdd(&g_P[s], fmaxf(xv,  0.f));
                atomicAdd(&g_M[s], fmaxf(-xv, 0.f));
            }
        }
    } else {
        // generic fallback (never taken for this problem's inputs)
        __shared__ float sw0[D], sb0[D], sW1[D * D], sb1[D];
        for (int i = tid; i < D; i += blockDim.x) {
            sw0[i] = w0[i]; sb0[i] = b0[i]; sb1[i] = b1[i];
        }
        for (int i = tid; i < D * D; i += blockDim.x) sW1[i] = W1[i];
        __syncthreads();

        const int stride = gridDim.x * blockDim.x;
        for (int i = blockIdx.x * blockDim.x + tid; i < n; i += stride) {
            float xv = x[i];
            int   e  = seg[i];
            float h1[D];
            #pragma unroll
            for (int j = 0; j < D; j++) h1[j] = fmaxf(xv * sw0[j] + sb0[j], 0.f);
            #pragma unroll 2
            for (int k = 0; k < D; k++) {
                float acc = sb1[k];
                #pragma unroll
                for (int j = 0; j < D; j++) acc += h1[j] * sW1[j * D + k];
                atomicAdd(&g_pooled[e * D + k], fmaxf(acc, 0.f));
            }
        }
    }
}

// ---------------- K2: mma.sync tf32 event MLP + global sum + final ----------------
__global__ void __launch_bounds__(EV_THR) k_events_mma(
    const float* __restrict__ r1w0, const float* __restrict__ r1b0,
    const float* __restrict__ r1w1, const float* __restrict__ r1b1,
    const float* __restrict__ o1w,  const float* __restrict__ o1b,
    const float* __restrict__ p2w0, const float* __restrict__ p2b0,
    const float* __restrict__ p2w1, const float* __restrict__ p2b1,
    const float* __restrict__ r2w0, const float* __restrict__ r2b0,
    const float* __restrict__ r2w1, const float* __restrict__ r2b1,
    const float* __restrict__ o2w,  const float* __restrict__ o2b,
    float* __restrict__ out)
{
    extern __shared__ __align__(16) char dsm[];
    float*  sA   = (float*)(dsm + SM_A);
    float2* sWB  = (float2*)(dsm + SM_W);
    float*  sB   = (float*)(dsm + SM_B);
    float*  su   = (float*)(dsm + SM_UV);
    float*  sv   = (float*)(dsm + SM_UV + D * 4);
    float*  sb0f = (float*)(dsm + SM_UV + 2 * D * 4);
    int*    s_lastp = (int*)(dsm + SM_LAST);

    const int tid  = threadIdx.x;
    const int wid  = tid >> 5;
    const int lane = tid & 31;
    const int gr   = lane >> 2;       // group id 0..7
    const int km   = lane & 3;        // thread-in-group 0..3
    const int e0   = blockIdx.x * EB;
    const int flag = g_flag;

    const float* Ws[5];
    const float* Bs[5];
    int NL;
    if (!flag) {
        Ws[0] = r1w1; Bs[0] = r1b1;
        Ws[1] = o1w;  Bs[1] = o1b;
        Ws[2] = p2w0; Bs[2] = p2b0;
        Ws[3] = p2w1; Bs[3] = p2b1;
        NL = 4;
    } else {
        Ws[0] = r1w0; Bs[0] = r1b0;
        Ws[1] = r1w1; Bs[1] = r1b1;
        Ws[2] = o1w;  Bs[2] = o1b;
        Ws[3] = p2w0; Bs[3] = p2b0;
        Ws[4] = p2w1; Bs[4] = p2b1;
        NL = 5;
    }

    // pack weights: sWB[L][kstep][km2][n] = (W[kstep*8+km2][n], W[kstep*8+km2+4][n]), tf32-rounded
    for (int L = 0; L < NL; L++) {
        const float* W = Ws[L];
        #pragma unroll
        for (int i = tid; i < D * D; i += EV_THR) {
            int k = i >> 6, nn = i & 63;          // coalesced over nn
            float w = W[k * D + nn];
            int kstep = k >> 3, km2 = k & 3, kh = (k >> 2) & 1;
            float* dst = (float*)&sWB[L * LW_F2 + kstep * (4 * KMST) + km2 * KMST + nn];
            dst[kh] = __uint_as_float(tf32r(w));
        }
    }
    for (int i = tid; i < NL * D; i += EV_THR) sB[i] = Bs[i >> 6][i & 63];
    if (tid < D) { su[tid] = g_u[tid]; sv[tid] = g_v[tid]; sb0f[tid] = r1b0[tid]; }
    __syncthreads();

    // build A tile [64 rows][64 cols], stride AST, tf32-rounded
    {
        const int row = tid & 63;
        const int c0 = (tid >> 6) * 16;
        if (!flag) {
            float P = __ldcg(&g_P[e0 + row]);
            float M = __ldcg(&g_M[e0 + row]);
            #pragma unroll
            for (int c = c0; c < c0 + 16; c++) {
                float h = fmaxf(P * su[c] + M * sv[c] + sb0f[c], 0.f);
                sA[row * AST + c] = __uint_as_float(tf32r(h));
            }
        } else {
            #pragma unroll
            for (int c = c0; c < c0 + 16; c++) {
                float h = __ldcg(&g_pooled[(e0 + row) * D + c]);
                sA[row * AST + c] = __uint_as_float(tf32r(h));
            }
        }
    }
    __syncthreads();

    // warp work split: m-tile = wid>>1 (16 events), n-half = wid&1 (32 cols, 4 n-tiles)
    const int e0r = (wid >> 1) * 16;
    const int nh  = (wid & 1) * 32;

    for (int L = 0; L < NL; L++) {
        float c0[4], c1[4], c2[4], c3[4];
        #pragma unroll
        for (int t = 0; t < 4; t++) { c0[t] = c1[t] = c2[t] = c3[t] = 0.f; }

        const float* rowA = sA + (e0r + gr) * AST;
        const float* rowB = rowA + 8 * AST;
        const float2* pWL = sWB + L * LW_F2 + km * KMST;

        #pragma unroll
        for (int ks = 0; ks < 8; ks++) {
            const int k0 = ks * 8;
            uint32_t a0 = __float_as_uint(rowA[k0 + km]);
            uint32_t a1 = __float_as_uint(rowB[k0 + km]);
            uint32_t a2 = __float_as_uint(rowA[k0 + km + 4]);
            uint32_t a3 = __float_as_uint(rowB[k0 + km + 4]);
            const float2* pk = pWL + ks * (4 * KMST);
            #pragma unroll
            for (int t = 0; t < 4; t++) {
                float2 b = pk[nh + t * 8 + gr];
                mma_tf32(c0[t], c1[t], c2[t], c3[t], a0, a1, a2, a3,
                         __float_as_uint(b.x), __float_as_uint(b.y));
            }
        }

        __syncthreads();   // everyone done reading sA

        if (L < NL - 1) {
            // epilogue: bias + relu + tf32 round, store back to sA
            #pragma unroll
            for (int t = 0; t < 4; t++) {
                int nc = nh + t * 8 + 2 * km;
                float2 b = *(const float2*)&sB[L * D + nc];
                float2 v0, v1;
                v0.x = __uint_as_float(tf32r(fmaxf(c0[t] + b.x, 0.f)));
                v0.y = __uint_as_float(tf32r(fmaxf(c1[t] + b.y, 0.f)));
                v1.x = __uint_as_float(tf32r(fmaxf(c2[t] + b.x, 0.f)));
                v1.y = __uint_as_float(tf32r(fmaxf(c3[t] + b.y, 0.f)));
                *(float2*)&sA[(e0r + gr) * AST + nc]     = v0;
                *(float2*)&sA[(e0r + gr + 8) * AST + nc] = v1;
            }
            __syncthreads();
        } else {
            // last layer: bias + relu, store fp32 exact
            #pragma unroll
            for (int t = 0; t < 4; t++) {
                int nc = nh + t * 8 + 2 * km;
                float2 b = *(const float2*)&sB[L * D + nc];
                float2 v0, v1;
                v0.x = fmaxf(c0[t] + b.x, 0.f);
                v0.y = fmaxf(c1[t] + b.y, 0.f);
                v1.x = fmaxf(c2[t] + b.x, 0.f);
                v1.y = fmaxf(c3[t] + b.y, 0.f);
                *(float2*)&sA[(e0r + gr) * AST + nc]     = v0;
                *(float2*)&sA[(e0r + gr + 8) * AST + nc] = v1;
            }
            __syncthreads();
        }
    }

    // column sums over this block's 64 events -> atomic into g_gsum
    if (tid < D) {
        float s = 0.f;
        #pragma unroll 8
        for (int r = 0; r < EB; r++) s += sA[r * AST + tid];
        atomicAdd(&g_gsum[tid], s);
    }

    // ---- last-block ticket: rho2 + output ----
    __threadfence();
    __syncthreads();
    if (tid == 0) {
        int old = atomicAdd(&g_cnt, 1);
        *s_lastp = (old == NBLK_EV - 1);
    }
    __syncthreads();

    if (*s_lastp) {
        float* sf0 = sA;              // reuse A region
        float* sf1 = sA + D;
        float* sf2 = sA + 2 * D;
        if (tid < D) sf0[tid] = __ldcg(&g_gsum[tid]);
        __syncthreads();
        if (tid < D) {
            float a = r2b0[tid];
            #pragma unroll
            for (int j = 0; j < D; j++) a += sf0[j] * r2w0[j * D + tid];
            sf1[tid] = fmaxf(a, 0.f);
        }
        __syncthreads();
        if (tid < D) {
            float a = r2b1[tid];
            #pragma unroll
            for (int j = 0; j < D; j++) a += sf1[j] * r2w1[j * D + tid];
            sf2[tid] = fmaxf(a, 0.f);
        }
        __syncthreads();
        if (tid < 10) {
            float a = o2b[tid];
            #pragma unroll
            for (int j = 0; j < D; j++) a += sf2[j] * o2w[j * 10 + tid];
            out[tid] = a;
        }
        if (tid == 0) g_cnt = 0;      // self-reset for next replay
    }
}

// ---------------- launch ----------------
extern "C" void kernel_launch(void* const* d_in, const int* in_sizes, int n_in,
                              void* d_out, int out_size)
{
    const float* x    = (const float*)d_in[0];
    const int*   seg  = (const int*)  d_in[1];
    const float* p1w0 = (const float*)d_in[2];
    const float* p1b0 = (const float*)d_in[3];
    const float* p1w1 = (const float*)d_in[4];
    const float* p1b1 = (const float*)d_in[5];
    const float* r1w0 = (const float*)d_in[6];
    const float* r1b0 = (const float*)d_in[7];
    const float* r1w1 = (const float*)d_in[8];
    const float* r1b1 = (const float*)d_in[9];
    const float* o1w  = (const float*)d_in[10];
    const float* o1b  = (const float*)d_in[11];
    const float* p2w0 = (const float*)d_in[12];
    const float* p2b0 = (const float*)d_in[13];
    const float* p2w1 = (const float*)d_in[14];
    const float* p2b1 = (const float*)d_in[15];
    const float* r2w0 = (const float*)d_in[16];
    const float* r2b0 = (const float*)d_in[17];
    const float* r2w1 = (const float*)d_in[18];
    const float* r2b1 = (const float*)d_in[19];
    const float* o2w  = (const float*)d_in[20];
    const float* o2b  = (const float*)d_in[21];
    const int n = in_sizes[0];

    cudaFuncSetAttribute(k_events_mma,
                         cudaFuncAttributeMaxDynamicSharedMemorySize, SMEM_EV);

    void* zp = nullptr;
    cudaGetSymbolAddress(&zp, g_zero);
    cudaMemsetAsync(zp, 0, sizeof(float) * (2 * E_NUM + D + E_NUM * D));

    k_stage1<<<S1_BLOCKS, 256>>>(x, seg, n, p1w0, p1b0, p1w1, p1b1, r1w0);
    k_events_mma<<<NBLK_EV, EV_THR, SMEM_EV>>>(r1w0, r1b0, r1w1, r1b1, o1w, o1b,
                                               p2w0, p2b0, p2w1, p2b1,
                                               r2w0, r2b0, r2w1, r2b1,
                                               o2w, o2b, (float*)d_out);
}

// round 17
// speedup vs baseline: 1.1823x; 1.0840x over previous
#include <cuda_runtime.h>
#include <cstdint>

#define E_NUM 8192
#define D 64
#define S1_BLOCKS 592
#define EB 64                       // events per block
#define NBLK_EV (E_NUM / EB)        // 128
#define EV_THR 256
#define AST 68                      // A tile row stride (floats), conflict-free frags
#define LW_F2 2112                  // f2 per layer: 8 kstep * (4 km * 66)
#define KMST 66                     // km stride in f2

// ---- events-kernel dynamic smem layout (bytes) ----
#define SM_A    0                       // 64 * 68 * 4 = 17408
#define SM_W    17408                   // 5 * 2112 * 8 = 84480
#define SM_B    (SM_W + 5 * LW_F2 * 8)  // 5*64*4
#define SM_UV   (SM_B + 5 * D * 4)      // su, sv, sb0f
#define SM_LAST (SM_UV + 3 * D * 4)
#define SMEM_EV (SM_LAST + 16)

// ---------------- scratch (no allocs; zero-init at load; self-cleaned per replay) ----------------
__device__ float g_P[E_NUM];
__device__ float g_M[E_NUM];
__device__ float g_gsum[D];
__device__ float g_pooled[E_NUM * D];   // generic fallback only
__device__ int   g_cnt;

// ---- helpers ----
__device__ __forceinline__ uint32_t tf32r(float f)
{
    uint32_t r; asm("cvt.rna.tf32.f32 %0, %1;" : "=r"(r) : "f"(f)); return r;
}
__device__ __forceinline__ void mma_tf32(float& c0, float& c1, float& c2, float& c3,
                                         uint32_t a0, uint32_t a1, uint32_t a2, uint32_t a3,
                                         uint32_t b0, uint32_t b1)
{
    asm volatile(
        "mma.sync.aligned.m16n8k8.row.col.f32.tf32.tf32.f32 "
        "{%0,%1,%2,%3}, {%4,%5,%6,%7}, {%8,%9}, {%0,%1,%2,%3};"
        : "+f"(c0), "+f"(c1), "+f"(c2), "+f"(c3)
        : "r"(a0), "r"(a1), "r"(a2), "r"(a3), "r"(b0), "r"(b1));
}

// ---------------- K1: pure stage-1 segment sums ----------------
__global__ void __launch_bounds__(256) k_stage1(
    const float* __restrict__ x, const int* __restrict__ seg, int n,
    const float* __restrict__ w0, const float* __restrict__ b0,
    const float* __restrict__ W1, const float* __restrict__ b1)
{
#if __CUDA_ARCH__ >= 900
    cudaTriggerProgrammaticLaunchCompletion();   // let events kernel start its prep now
#endif
    const int tid = threadIdx.x;

    int nz = 0;
    if (tid < D) nz = (b0[tid] != 0.f) || (b1[tid] != 0.f);
    const int anyb = __syncthreads_or(nz);

    if (!anyb) {
        const int lane   = tid & 31;
        const int warp   = (blockIdx.x * blockDim.x + tid) >> 5;
        const int nwarps = (gridDim.x * blockDim.x) >> 5;
        const int G      = n >> 2;
        const int gpw    = (G + nwarps - 1) / nwarps;

        const long long gbase = (long long)warp * gpw;
        const long long gend0 = gbase + gpw;
        const long long gend  = gend0 < (long long)G ? gend0 : (long long)G;

        const float4* x4 = (const float4*)x;
        const int4*   s4 = (const int4*)seg;

        int   cur = -1;
        float S = 0.f, A = 0.f;

        auto process = [&](const float4& xv, const int4& sv4) {
            if ((sv4.x == sv4.w) && (sv4.x == cur)) {
                S += (xv.x + xv.y) + (xv.z + xv.w);
                A += (fabsf(xv.x) + fabsf(xv.y)) + (fabsf(xv.z) + fabsf(xv.w));
            } else {
                int   ss[4] = {sv4.x, sv4.y, sv4.z, sv4.w};
                float xs[4] = {xv.x, xv.y, xv.z, xv.w};
                #pragma unroll
                for (int u2 = 0; u2 < 4; u2++) {
                    if (ss[u2] != cur) {
                        if (cur >= 0) {
                            atomicAdd(&g_P[cur], 0.5f * (A + S));
                            atomicAdd(&g_M[cur], 0.5f * (A - S));
                        }
                        cur = ss[u2]; S = 0.f; A = 0.f;
                    }
                    S += xs[u2]; A += fabsf(xs[u2]);
                }
            }
        };

        long long g = gbase + lane;
        if (g < gend) {
            float4 xv = x4[g];
            int4   sv4 = s4[g];
            for (g += 32; g < gend; g += 32) {
                float4 xn = x4[g];          // prefetch next
                int4   sn = s4[g];
                process(xv, sv4);
                xv = xn; sv4 = sn;
            }
            process(xv, sv4);
            if (cur >= 0) {
                atomicAdd(&g_P[cur], 0.5f * (A + S));
                atomicAdd(&g_M[cur], 0.5f * (A - S));
            }
        }

        if (warp == 0 && lane == 0) {
            for (int i = G * 4; i < n; i++) {
                float xv = x[i]; int s = seg[i];
                atomicAdd(&g_P[s], fmaxf(xv,  0.f));
                atomicAdd(&g_M[s], fmaxf(-xv, 0.f));
            }
        }
    } else {
        // generic fallback (never taken for this dataset); g_pooled is zero by invariant
        __shared__ float sw0[D], sb0[D], sW1[D * D], sb1[D];
        for (int i = tid; i < D; i += blockDim.x) {
            sw0[i] = w0[i]; sb0[i] = b0[i]; sb1[i] = b1[i];
        }
        for (int i = tid; i < D * D; i += blockDim.x) sW1[i] = W1[i];
        __syncthreads();

        const int stride = gridDim.x * blockDim.x;
        for (int i = blockIdx.x * blockDim.x + tid; i < n; i += stride) {
            float xv = x[i];
            int   e  = seg[i];
            float h1[D];
            #pragma unroll
            for (int j = 0; j < D; j++) h1[j] = fmaxf(xv * sw0[j] + sb0[j], 0.f);
            #pragma unroll 2
            for (int k = 0; k < D; k++) {
                float acc = sb1[k];
                #pragma unroll
                for (int j = 0; j < D; j++) acc += h1[j] * sW1[j * D + k];
                atomicAdd(&g_pooled[e * D + k], fmaxf(acc, 0.f));
            }
        }
    }
}

// ---------------- K2: PDL-overlapped mma.sync tf32 event MLP + final ----------------
__global__ void __launch_bounds__(EV_THR) k_events_mma(
    const float* __restrict__ p1w0, const float* __restrict__ p1b0,
    const float* __restrict__ p1w1, const float* __restrict__ p1b1,
    const float* __restrict__ r1w0, const float* __restrict__ r1b0,
    const float* __restrict__ r1w1, const float* __restrict__ r1b1,
    const float* __restrict__ o1w,  const float* __restrict__ o1b,
    const float* __restrict__ p2w0, const float* __restrict__ p2b0,
    const float* __restrict__ p2w1, const float* __restrict__ p2b1,
    const float* __restrict__ r2w0, const float* __restrict__ r2b0,
    const float* __restrict__ r2w1, const float* __restrict__ r2b1,
    const float* __restrict__ o2w,  const float* __restrict__ o2b,
    float* __restrict__ out)
{
    extern __shared__ __align__(16) char dsm[];
    float*  sA   = (float*)(dsm + SM_A);
    float2* sWB  = (float2*)(dsm + SM_W);
    float*  sB   = (float*)(dsm + SM_B);
    float*  su   = (float*)(dsm + SM_UV);
    float*  sv   = (float*)(dsm + SM_UV + D * 4);
    float*  sb0f = (float*)(dsm + SM_UV + 2 * D * 4);
    int*    s_lastp = (int*)(dsm + SM_LAST);

    const int tid  = threadIdx.x;
    const int wid  = tid >> 5;
    const int lane = tid & 31;
    const int gr   = lane >> 2;
    const int km   = lane & 3;
    const int e0   = blockIdx.x * EB;

    // ======== PREP: independent of stage1 output — overlaps under PDL ========
    int nz = 0;
    if (tid < D) nz = (p1b0[tid] != 0.f) || (p1b1[tid] != 0.f);
    const int flag = __syncthreads_or(nz);

    const float* Ws[5];
    const float* Bs[5];
    int NL;
    if (!flag) {
        Ws[0] = r1w1; Bs[0] = r1b1;
        Ws[1] = o1w;  Bs[1] = o1b;
        Ws[2] = p2w0; Bs[2] = p2b0;
        Ws[3] = p2w1; Bs[3] = p2b1;
        NL = 4;
    } else {
        Ws[0] = r1w0; Bs[0] = r1b0;
        Ws[1] = r1w1; Bs[1] = r1b1;
        Ws[2] = o1w;  Bs[2] = o1b;
        Ws[3] = p2w0; Bs[3] = p2b0;
        Ws[4] = p2w1; Bs[4] = p2b1;
        NL = 5;
    }

    // pack weights tf32 into mma-B layout
    for (int L = 0; L < NL; L++) {
        const float* W = Ws[L];
        #pragma unroll
        for (int i = tid; i < D * D; i += EV_THR) {
            int k = i >> 6, nn = i & 63;
            float w = W[k * D + nn];
            int kstep = k >> 3, km2 = k & 3, kh = (k >> 2) & 1;
            float* dst = (float*)&sWB[L * LW_F2 + kstep * (4 * KMST) + km2 * KMST + nn];
            dst[kh] = __uint_as_float(tf32r(w));
        }
    }
    for (int i = tid; i < NL * D; i += EV_THR) sB[i] = Bs[i >> 6][i & 63];
    if (tid < D) sb0f[tid] = r1b0[tid];

    // u,v from weights only (temp in sA; overwritten later)
    {
        float* scp = sA;
        float* scm = sA + D;
        if (tid < D) {
            float vp = 0.f, vn = 0.f;
            #pragma unroll
            for (int j = 0; j < D; j++) {
                float w   = p1w0[j];
                float col = p1w1[j * D + tid];
                vp += fmaxf(w, 0.f)  * col;
                vn += fmaxf(-w, 0.f) * col;
            }
            scp[tid] = fmaxf(vp, 0.f);
            scm[tid] = fmaxf(vn, 0.f);
        }
        __syncthreads();
        if (tid < D) {
            float u = 0.f, v = 0.f;
            #pragma unroll
            for (int j = 0; j < D; j++) {
                float w = r1w0[j * D + tid];
                u += scp[j] * w;
                v += scm[j] * w;
            }
            su[tid] = u;
            sv[tid] = v;
        }
        __syncthreads();
    }

    // ======== wait for stage1 (PDL) ========
#if __CUDA_ARCH__ >= 900
    cudaGridDependencySynchronize();
#endif

    // build A tile [64 rows][64 cols], stride AST, tf32-rounded
    {
        const int row = tid & 63;
        const int c0 = (tid >> 6) * 16;
        if (!flag) {
            float P = __ldcg(&g_P[e0 + row]);
            float M = __ldcg(&g_M[e0 + row]);
            #pragma unroll
            for (int c = c0; c < c0 + 16; c++) {
                float h = fmaxf(P * su[c] + M * sv[c] + sb0f[c], 0.f);
                sA[row * AST + c] = __uint_as_float(tf32r(h));
            }
        } else {
            #pragma unroll
            for (int c = c0; c < c0 + 16; c++) {
                float h = __ldcg(&g_pooled[(e0 + row) * D + c]);
                sA[row * AST + c] = __uint_as_float(tf32r(h));
            }
        }
    }
    __syncthreads();

    // self-clean consumed scratch for next replay
    if (!flag) {
        if (tid < EB)            g_P[e0 + tid] = 0.f;
        else if (tid < 2 * EB)   g_M[e0 + tid - EB] = 0.f;
    } else {
        for (int i = tid; i < EB * D; i += EV_THR) g_pooled[e0 * D + i] = 0.f;
    }

    // warp split: m-tile = wid>>1 (16 events), n-half = wid&1 (32 cols)
    const int e0r = (wid >> 1) * 16;
    const int nh  = (wid & 1) * 32;

    for (int L = 0; L < NL; L++) {
        float c0[4], c1[4], c2[4], c3[4];
        #pragma unroll
        for (int t = 0; t < 4; t++) { c0[t] = c1[t] = c2[t] = c3[t] = 0.f; }

        const float* rowA = sA + (e0r + gr) * AST;
        const float* rowB = rowA + 8 * AST;
        const float2* pWL = sWB + L * LW_F2 + km * KMST;

        #pragma unroll
        for (int ks = 0; ks < 8; ks++) {
            const int k0 = ks * 8;
            uint32_t a0 = __float_as_uint(rowA[k0 + km]);
            uint32_t a1 = __float_as_uint(rowB[k0 + km]);
            uint32_t a2 = __float_as_uint(rowA[k0 + km + 4]);
            uint32_t a3 = __float_as_uint(rowB[k0 + km + 4]);
            const float2* pk = pWL + ks * (4 * KMST);
            #pragma unroll
            for (int t = 0; t < 4; t++) {
                float2 b = pk[nh + t * 8 + gr];
                mma_tf32(c0[t], c1[t], c2[t], c3[t], a0, a1, a2, a3,
                         __float_as_uint(b.x), __float_as_uint(b.y));
            }
        }

        __syncthreads();

        if (L < NL - 1) {
            #pragma unroll
            for (int t = 0; t < 4; t++) {
                int nc = nh + t * 8 + 2 * km;
                float2 b = *(const float2*)&sB[L * D + nc];
                float2 v0, v1;
                v0.x = __uint_as_float(tf32r(fmaxf(c0[t] + b.x, 0.f)));
                v0.y = __uint_as_float(tf32r(fmaxf(c1[t] + b.y, 0.f)));
                v1.x = __uint_as_float(tf32r(fmaxf(c2[t] + b.x, 0.f)));
                v1.y = __uint_as_float(tf32r(fmaxf(c3[t] + b.y, 0.f)));
                *(float2*)&sA[(e0r + gr) * AST + nc]     = v0;
                *(float2*)&sA[(e0r + gr + 8) * AST + nc] = v1;
            }
            __syncthreads();
        } else {
            #pragma unroll
            for (int t = 0; t < 4; t++) {
                int nc = nh + t * 8 + 2 * km;
                float2 b = *(const float2*)&sB[L * D + nc];
                float2 v0, v1;
                v0.x = fmaxf(c0[t] + b.x, 0.f);
                v0.y = fmaxf(c1[t] + b.y, 0.f);
                v1.x = fmaxf(c2[t] + b.x, 0.f);
                v1.y = fmaxf(c3[t] + b.y, 0.f);
                *(float2*)&sA[(e0r + gr) * AST + nc]     = v0;
                *(float2*)&sA[(e0r + gr + 8) * AST + nc] = v1;
            }
            __syncthreads();
        }
    }

    // column sums -> atomic into g_gsum
    if (tid < D) {
        float s = 0.f;
        #pragma unroll 8
        for (int r = 0; r < EB; r++) s += sA[r * AST + tid];
        atomicAdd(&g_gsum[tid], s);
    }

    // ---- last-block ticket: rho2 + output ----
    __threadfence();
    __syncthreads();
    if (tid == 0) {
        int old = atomicAdd(&g_cnt, 1);
        *s_lastp = (old == NBLK_EV - 1);
    }
    __syncthreads();

    if (*s_lastp) {
        float* sf0 = sA;
        float* sf1 = sA + D;
        float* sf2 = sA + 2 * D;
        if (tid < D) {
            sf0[tid] = __ldcg(&g_gsum[tid]);
            g_gsum[tid] = 0.f;        // self-clean for next replay
        }
        __syncthreads();
        if (tid < D) {
            float a = r2b0[tid];
            #pragma unroll
            for (int j = 0; j < D; j++) a += sf0[j] * r2w0[j * D + tid];
            sf1[tid] = fmaxf(a, 0.f);
        }
        __syncthreads();
        if (tid < D) {
            float a = r2b1[tid];
            #pragma unroll
            for (int j = 0; j < D; j++) a += sf1[j] * r2w1[j * D + tid];
            sf2[tid] = fmaxf(a, 0.f);
        }
        __syncthreads();
        if (tid < 10) {
            float a = o2b[tid];
            #pragma unroll
            for (int j = 0; j < D; j++) a += sf2[j] * o2w[j * 10 + tid];
            out[tid] = a;
        }
        if (tid == 0) g_cnt = 0;      // self-reset
    }
}

// ---------------- launch ----------------
extern "C" void kernel_launch(void* const* d_in, const int* in_sizes, int n_in,
                              void* d_out, int out_size)
{
    const float* x    = (const float*)d_in[0];
    const int*   seg  = (const int*)  d_in[1];
    const float* p1w0 = (const float*)d_in[2];
    const float* p1b0 = (const float*)d_in[3];
    const float* p1w1 = (const float*)d_in[4];
    const float* p1b1 = (const float*)d_in[5];
    const float* r1w0 = (const float*)d_in[6];
    const float* r1b0 = (const float*)d_in[7];
    const float* r1w1 = (const float*)d_in[8];
    const float* r1b1 = (const float*)d_in[9];
    const float* o1w  = (const float*)d_in[10];
    const float* o1b  = (const float*)d_in[11];
    const float* p2w0 = (const float*)d_in[12];
    const float* p2b0 = (const float*)d_in[13];
    const float* p2w1 = (const float*)d_in[14];
    const float* p2b1 = (const float*)d_in[15];
    const float* r2w0 = (const float*)d_in[16];
    const float* r2b0 = (const float*)d_in[17];
    const float* r2w1 = (const float*)d_in[18];
    const float* r2b1 = (const float*)d_in[19];
    const float* o2w  = (const float*)d_in[20];
    const float* o2b  = (const float*)d_in[21];
    const int n = in_sizes[0];

    cudaFuncSetAttribute(k_events_mma,
                         cudaFuncAttributeMaxDynamicSharedMemorySize, SMEM_EV);

    // node 1: stage1 (triggers PDL completion early)
    k_stage1<<<S1_BLOCKS, 256>>>(x, seg, n, p1w0, p1b0, p1w1, p1b1);

    // node 2: events — programmatic dependent launch (prep overlaps stage1)
    cudaLaunchConfig_t cfg = {};
    cfg.gridDim  = dim3(NBLK_EV, 1, 1);
    cfg.blockDim = dim3(EV_THR, 1, 1);
    cfg.dynamicSmemBytes = SMEM_EV;
    cfg.stream = 0;
    cudaLaunchAttribute attrs[1];
    attrs[0].id = cudaLaunchAttributeProgrammaticStreamSerialization;
    attrs[0].val.programmaticStreamSerializationAllowed = 1;
    cfg.attrs = attrs;
    cfg.numAttrs = 1;
    cudaLaunchKernelEx(&cfg, k_events_mma,
                       p1w0, p1b0, p1w1, p1b1,
                       r1w0, r1b0, r1w1, r1b1,
                       o1w, o1b, p2w0, p2b0, p2w1, p2b1,
                       r2w0, r2b0, r2w1, r2b1,
                       o2w, o2b, (float*)d_out);
}